// round 5
// baseline (speedup 1.0000x reference)
#include <cuda_runtime.h>

#define NTH 256
#define BT  32

// Pre-transposed weights: [k (128)][j (512)] layout for vectorized pair loads.
// 0: enc_Whh0, 1: enc_Wih1, 2: enc_Whh1, 3: dec_Whh0, 4: dec_Wih1, 5: dec_Whh1
__device__ float g_WT[6][128 * 512];

__global__ void transpose_w(const float* __restrict__ a, const float* __restrict__ b,
                            const float* __restrict__ c, const float* __restrict__ d,
                            const float* __restrict__ e, const float* __restrict__ f)
{
    int idx = blockIdx.x * blockDim.x + threadIdx.x;   // 6 * 65536 total
    int m = idx >> 16;
    int r = idx & 65535;
    int j = r >> 7;       // 0..511
    int k = r & 127;      // 0..127
    const float* src;
    switch (m) {
        case 0: src = a; break;
        case 1: src = b; break;
        case 2: src = c; break;
        case 3: src = d; break;
        case 4: src = e; break;
        default: src = f; break;
    }
    g_WT[m][k * 512 + j] = src[j * 128 + k];
}

struct SM {
    float h0s[32][128];
    float h1s[32][128];
    float c0s[32][128];
    float c1s[32][128];
    float xs[32][90];
    float xcur[32][3];
    float wih0s[512 * 3];
    float b0s[512];
    float b1s[512];
    float fcWs[6 * 128];
    float fcbs[8];
};

__device__ __forceinline__ unsigned long long pk2(float lo, float hi) {
    unsigned long long v;
    asm("mov.b64 %0, {%1, %2};" : "=l"(v) : "f"(lo), "f"(hi));
    return v;
}
__device__ __forceinline__ float2 up2(unsigned long long v) {
    float2 f;
    asm("mov.b64 {%0, %1}, %2;" : "=f"(f.x), "=f"(f.y) : "l"(v));
    return f;
}
__device__ __forceinline__ float sigm(float x) {
    return __fdividef(1.0f, 1.0f + __expf(-x));
}
__device__ __forceinline__ float tanh_(float x) {
    // tanh(x) = 2*sigmoid(2x) - 1  (fast, rel-err ~1e-7 — well under tolerance)
    return 2.0f * sigm(2.0f * x) - 1.0f;
}

// acc[g*8 + r] accumulates gate pair (hh0, hh0+1) for row r0+r, gate block g.
// gates += WT^T-style matvec: for each k, acc += W[k][j..j+1] * h[row][k]
__device__ __forceinline__ void mv128(const float* __restrict__ WT,
                                      const float (*__restrict__ hs)[128],
                                      int r0, int hh0,
                                      unsigned long long* acc)
{
    const float* wp = WT + hh0;
#pragma unroll 2
    for (int k = 0; k < 128; ++k) {
        const float* wk = wp + k * 512;
        unsigned long long w0 = *(const unsigned long long*)(wk);
        unsigned long long w1 = *(const unsigned long long*)(wk + 128);
        unsigned long long w2 = *(const unsigned long long*)(wk + 256);
        unsigned long long w3 = *(const unsigned long long*)(wk + 384);
#pragma unroll
        for (int r = 0; r < 8; ++r) {
            float hv = hs[r0 + r][k];
            unsigned long long hp;
            asm("mov.b64 %0, {%1, %1};" : "=l"(hp) : "f"(hv));
            asm("fma.rn.f32x2 %0, %1, %2, %0;" : "+l"(acc[0 * 8 + r]) : "l"(w0), "l"(hp));
            asm("fma.rn.f32x2 %0, %1, %2, %0;" : "+l"(acc[1 * 8 + r]) : "l"(w1), "l"(hp));
            asm("fma.rn.f32x2 %0, %1, %2, %0;" : "+l"(acc[2 * 8 + r]) : "l"(w2), "l"(hp));
            asm("fma.rn.f32x2 %0, %1, %2, %0;" : "+l"(acc[3 * 8 + r]) : "l"(w3), "l"(hp));
        }
    }
}

__device__ __forceinline__ void gate_update(const unsigned long long* acc,
                                            float (*__restrict__ cs)[128],
                                            float (*__restrict__ hsout)[128],
                                            int r0, int hh0)
{
#pragma unroll
    for (int r = 0; r < 8; ++r) {
        float2 gi = up2(acc[0 * 8 + r]);
        float2 gf = up2(acc[1 * 8 + r]);
        float2 gg = up2(acc[2 * 8 + r]);
        float2 go = up2(acc[3 * 8 + r]);
        float2 c = *(float2*)&cs[r0 + r][hh0];
        float cx = sigm(gf.x) * c.x + sigm(gi.x) * tanh_(gg.x);
        float cy = sigm(gf.y) * c.y + sigm(gi.y) * tanh_(gg.y);
        float hx = sigm(go.x) * tanh_(cx);
        float hy = sigm(go.y) * tanh_(cy);
        *(float2*)&cs[r0 + r][hh0] = make_float2(cx, cy);
        *(float2*)&hsout[r0 + r][hh0] = make_float2(hx, hy);
    }
}

// One full 2-layer LSTM timestep for this CTA's 32 rows.
__device__ __forceinline__ void step(SM* sm, const float xr[8][3],
                                     const float* __restrict__ WThh0,
                                     const float* __restrict__ WTih1,
                                     const float* __restrict__ WThh1,
                                     int r0, int hh0)
{
    unsigned long long acc[32];

    // ---- layer 0: init with bias + Wih0 @ x (input dim 3) ----
#pragma unroll
    for (int g = 0; g < 4; ++g) {
        const int j = g * 128 + hh0;
        const float bl = sm->b0s[j];
        const float bh = sm->b0s[j + 1];
        const float* wl = &sm->wih0s[j * 3];
        float wl0 = wl[0], wl1 = wl[1], wl2 = wl[2];
        float wh0 = wl[3], wh1 = wl[4], wh2 = wl[5];
#pragma unroll
        for (int r = 0; r < 8; ++r) {
            float lo = bl + wl0 * xr[r][0] + wl1 * xr[r][1] + wl2 * xr[r][2];
            float hi = bh + wh0 * xr[r][0] + wh1 * xr[r][1] + wh2 * xr[r][2];
            acc[g * 8 + r] = pk2(lo, hi);
        }
    }
    mv128(WThh0, sm->h0s, r0, hh0, acc);
    __syncthreads();                       // everyone done reading old h0
    gate_update(acc, sm->c0s, sm->h0s, r0, hh0);
    __syncthreads();                       // new h0 visible

    // ---- layer 1: init with bias, then Wih1 @ h0_new + Whh1 @ h1_old ----
#pragma unroll
    for (int g = 0; g < 4; ++g) {
        const int j = g * 128 + hh0;
        unsigned long long bv = pk2(sm->b1s[j], sm->b1s[j + 1]);
#pragma unroll
        for (int r = 0; r < 8; ++r) acc[g * 8 + r] = bv;
    }
    mv128(WTih1, sm->h0s, r0, hh0, acc);
    mv128(WThh1, sm->h1s, r0, hh0, acc);
    __syncthreads();                       // everyone done reading old h1
    gate_update(acc, sm->c1s, sm->h1s, r0, hh0);
    __syncthreads();                       // new h1 visible
}

__global__ void __launch_bounds__(NTH, 2)
lstm_kernel(const float* __restrict__ x,
            const float* __restrict__ eWih0, const float* __restrict__ eb0,
            const float* __restrict__ eb1,
            const float* __restrict__ dWih0, const float* __restrict__ db0,
            const float* __restrict__ db1,
            const float* __restrict__ fcW, const float* __restrict__ fcb,
            float* __restrict__ out, int B)
{
    extern __shared__ char smraw[];
    SM* sm = (SM*)smraw;

    const int tid = threadIdx.x;
    const int r0 = (tid >> 6) * 8;        // 4 row groups of 8 rows
    const int hh0 = (tid & 63) * 2;       // 64 hidden groups of 2
    const int bbase = blockIdx.x * BT;

    // Load this tile's input sequence (coalesced)
    for (int i = tid; i < BT * 90; i += NTH)
        sm->xs[i / 90][i % 90] = x[(size_t)(bbase + i / 90) * 90 + (i % 90)];
    for (int i = tid; i < 768; i += NTH) sm->fcWs[i] = fcW[i];
    if (tid < 6) sm->fcbs[tid] = fcb[tid];
    // encoder small weights
    for (int i = tid; i < 1536; i += NTH) sm->wih0s[i] = eWih0[i];
    for (int i = tid; i < 512; i += NTH) { sm->b0s[i] = eb0[i]; sm->b1s[i] = eb1[i]; }
    // zero states
#pragma unroll
    for (int r = 0; r < 8; ++r) {
        *(float2*)&sm->h0s[r0 + r][hh0] = make_float2(0.f, 0.f);
        *(float2*)&sm->h1s[r0 + r][hh0] = make_float2(0.f, 0.f);
        *(float2*)&sm->c0s[r0 + r][hh0] = make_float2(0.f, 0.f);
        *(float2*)&sm->c1s[r0 + r][hh0] = make_float2(0.f, 0.f);
    }
    __syncthreads();

    // ---------------- encoder ----------------
    for (int t = 0; t < 30; ++t) {
        float xr[8][3];
#pragma unroll
        for (int r = 0; r < 8; ++r) {
            xr[r][0] = sm->xs[r0 + r][3 * t + 0];
            xr[r][1] = sm->xs[r0 + r][3 * t + 1];
            xr[r][2] = sm->xs[r0 + r][3 * t + 2];
        }
        step(sm, xr, g_WT[0], g_WT[1], g_WT[2], r0, hh0);
    }

    // swap in decoder small weights; seed decoder input with x[:, -1, :]
    for (int i = tid; i < 1536; i += NTH) sm->wih0s[i] = dWih0[i];
    for (int i = tid; i < 512; i += NTH) { sm->b0s[i] = db0[i]; sm->b1s[i] = db1[i]; }
    if (tid < 96) sm->xcur[tid / 3][tid % 3] = sm->xs[tid / 3][87 + (tid % 3)];
    __syncthreads();

    // ---------------- decoder ----------------
    const size_t logvar_off = (size_t)B * 90;
    for (int t = 0; t < 30; ++t) {
        float xr[8][3];
#pragma unroll
        for (int r = 0; r < 8; ++r) {
            xr[r][0] = sm->xcur[r0 + r][0];
            xr[r][1] = sm->xcur[r0 + r][1];
            xr[r][2] = sm->xcur[r0 + r][2];
        }
        step(sm, xr, g_WT[3], g_WT[4], g_WT[5], r0, hh0);

        // fc: stats = h1 @ fc_W^T + fc_b  (6 outputs x 32 rows = 192 threads)
        if (tid < 192) {
            int row = tid & 31;
            int o = tid >> 5;     // 0..5
            const float* w = &sm->fcWs[o * 128];
            const float* hv = sm->h1s[row];
            float s0 = 0.f, s1 = 0.f, s2 = 0.f, s3 = 0.f;
#pragma unroll 8
            for (int k = 0; k < 128; k += 4) {
                s0 += w[k] * hv[k];
                s1 += w[k + 1] * hv[k + 1];
                s2 += w[k + 2] * hv[k + 2];
                s3 += w[k + 3] * hv[k + 3];
            }
            float s = sm->fcbs[o] + (s0 + s1) + (s2 + s3);
            size_t base = ((size_t)(bbase + row) * 30 + t) * 3;
            if (o < 3) {
                out[base + o] = s;
                sm->xcur[row][o] = s;      // feedback for next step
            } else {
                out[logvar_off + base + (o - 3)] = s;
            }
        }
        __syncthreads();   // xcur visible for next timestep
    }
}

extern "C" void kernel_launch(void* const* d_in, const int* in_sizes, int n_in,
                              void* d_out, int out_size)
{
    const float* x     = (const float*)d_in[0];
    const float* eWih0 = (const float*)d_in[1];
    const float* eWhh0 = (const float*)d_in[2];
    const float* eb0   = (const float*)d_in[3];
    const float* eWih1 = (const float*)d_in[4];
    const float* eWhh1 = (const float*)d_in[5];
    const float* eb1   = (const float*)d_in[6];
    const float* dWih0 = (const float*)d_in[7];
    const float* dWhh0 = (const float*)d_in[8];
    const float* db0   = (const float*)d_in[9];
    const float* dWih1 = (const float*)d_in[10];
    const float* dWhh1 = (const float*)d_in[11];
    const float* db1   = (const float*)d_in[12];
    const float* fcW   = (const float*)d_in[13];
    const float* fcb   = (const float*)d_in[14];
    float* out = (float*)d_out;

    int B = in_sizes[0] / 90;   // T_IN * IN_DIM = 90

    cudaFuncSetAttribute(lstm_kernel, cudaFuncAttributeMaxDynamicSharedMemorySize,
                         (int)sizeof(SM));

    // Pre-transpose the six 512x128 matrices to [k][j] layout.
    transpose_w<<<(6 * 65536) / 256, 256>>>(eWhh0, eWih1, eWhh1, dWhh0, dWih1, dWhh1);

    lstm_kernel<<<B / BT, NTH, sizeof(SM)>>>(x, eWih0, eb0, eb1, dWih0, db0, db1,
                                             fcW, fcb, out, B);
}

// round 6
// speedup vs baseline: 1.0018x; 1.0018x over previous
#include <cuda_runtime.h>

#define NTH 256
#define BT  32

// Pre-transposed weights: [k (128)][j (512)] layout for vectorized pair loads.
// 0: enc_Whh0, 1: enc_Wih1, 2: enc_Whh1, 3: dec_Whh0, 4: dec_Wih1, 5: dec_Whh1
__device__ float g_WT[6][128 * 512];

__global__ void transpose_w(const float* __restrict__ a, const float* __restrict__ b,
                            const float* __restrict__ c, const float* __restrict__ d,
                            const float* __restrict__ e, const float* __restrict__ f)
{
    int idx = blockIdx.x * blockDim.x + threadIdx.x;   // 6 * 65536 total
    int m = idx >> 16;
    int r = idx & 65535;
    int j = r >> 7;       // 0..511
    int k = r & 127;      // 0..127
    const float* src;
    switch (m) {
        case 0: src = a; break;
        case 1: src = b; break;
        case 2: src = c; break;
        case 3: src = d; break;
        case 4: src = e; break;
        default: src = f; break;
    }
    g_WT[m][k * 512 + j] = src[j * 128 + k];
}

struct SM {
    float h0s[32][128];
    float h1s[32][128];
    float c0s[32][128];
    float c1s[32][128];
    float xs[32][90];
    float xcur[32][3];
    float wih0s[512 * 3];
    float b0s[512];
    float b1s[512];
    float fcWs[6 * 128];
    float fcbs[8];
};

__device__ __forceinline__ unsigned long long pk2(float lo, float hi) {
    unsigned long long v;
    asm("mov.b64 %0, {%1, %2};" : "=l"(v) : "f"(lo), "f"(hi));
    return v;
}
__device__ __forceinline__ float2 up2(unsigned long long v) {
    float2 f;
    asm("mov.b64 {%0, %1}, %2;" : "=f"(f.x), "=f"(f.y) : "l"(v));
    return f;
}
__device__ __forceinline__ float sigm(float x) {
    return __fdividef(1.0f, 1.0f + __expf(-x));
}
__device__ __forceinline__ float tanh_(float x) {
    // tanh(x) = 2*sigmoid(2x) - 1  (fast, rel-err ~1e-7 — well under tolerance)
    return 2.0f * sigm(2.0f * x) - 1.0f;
}

// acc[g*8 + r] accumulates gate pair (hh0, hh0+1) for row r0+r, gate block g.
// gates += WT^T-style matvec: for each k, acc += W[k][j..j+1] * h[row][k]
__device__ __forceinline__ void mv128(const float* __restrict__ WT,
                                      const float (*__restrict__ hs)[128],
                                      int r0, int hh0,
                                      unsigned long long* acc)
{
    const float* wp = WT + hh0;
#pragma unroll 2
    for (int k = 0; k < 128; ++k) {
        const float* wk = wp + k * 512;
        unsigned long long w0 = *(const unsigned long long*)(wk);
        unsigned long long w1 = *(const unsigned long long*)(wk + 128);
        unsigned long long w2 = *(const unsigned long long*)(wk + 256);
        unsigned long long w3 = *(const unsigned long long*)(wk + 384);
#pragma unroll
        for (int r = 0; r < 8; ++r) {
            float hv = hs[r0 + r][k];
            unsigned long long hp;
            asm("mov.b64 %0, {%1, %1};" : "=l"(hp) : "f"(hv));
            asm("fma.rn.f32x2 %0, %1, %2, %0;" : "+l"(acc[0 * 8 + r]) : "l"(w0), "l"(hp));
            asm("fma.rn.f32x2 %0, %1, %2, %0;" : "+l"(acc[1 * 8 + r]) : "l"(w1), "l"(hp));
            asm("fma.rn.f32x2 %0, %1, %2, %0;" : "+l"(acc[2 * 8 + r]) : "l"(w2), "l"(hp));
            asm("fma.rn.f32x2 %0, %1, %2, %0;" : "+l"(acc[3 * 8 + r]) : "l"(w3), "l"(hp));
        }
    }
}

__device__ __forceinline__ void gate_update(const unsigned long long* acc,
                                            float (*__restrict__ cs)[128],
                                            float (*__restrict__ hsout)[128],
                                            int r0, int hh0)
{
#pragma unroll
    for (int r = 0; r < 8; ++r) {
        float2 gi = up2(acc[0 * 8 + r]);
        float2 gf = up2(acc[1 * 8 + r]);
        float2 gg = up2(acc[2 * 8 + r]);
        float2 go = up2(acc[3 * 8 + r]);
        float2 c = *(float2*)&cs[r0 + r][hh0];
        float cx = sigm(gf.x) * c.x + sigm(gi.x) * tanh_(gg.x);
        float cy = sigm(gf.y) * c.y + sigm(gi.y) * tanh_(gg.y);
        float hx = sigm(go.x) * tanh_(cx);
        float hy = sigm(go.y) * tanh_(cy);
        *(float2*)&cs[r0 + r][hh0] = make_float2(cx, cy);
        *(float2*)&hsout[r0 + r][hh0] = make_float2(hx, hy);
    }
}

// One full 2-layer LSTM timestep for this CTA's 32 rows.
__device__ __forceinline__ void step(SM* sm, const float xr[8][3],
                                     const float* __restrict__ WThh0,
                                     const float* __restrict__ WTih1,
                                     const float* __restrict__ WThh1,
                                     int r0, int hh0)
{
    unsigned long long acc[32];

    // ---- layer 0: init with bias + Wih0 @ x (input dim 3) ----
#pragma unroll
    for (int g = 0; g < 4; ++g) {
        const int j = g * 128 + hh0;
        const float bl = sm->b0s[j];
        const float bh = sm->b0s[j + 1];
        const float* wl = &sm->wih0s[j * 3];
        float wl0 = wl[0], wl1 = wl[1], wl2 = wl[2];
        float wh0 = wl[3], wh1 = wl[4], wh2 = wl[5];
#pragma unroll
        for (int r = 0; r < 8; ++r) {
            float lo = bl + wl0 * xr[r][0] + wl1 * xr[r][1] + wl2 * xr[r][2];
            float hi = bh + wh0 * xr[r][0] + wh1 * xr[r][1] + wh2 * xr[r][2];
            acc[g * 8 + r] = pk2(lo, hi);
        }
    }
    mv128(WThh0, sm->h0s, r0, hh0, acc);
    __syncthreads();                       // everyone done reading old h0
    gate_update(acc, sm->c0s, sm->h0s, r0, hh0);
    __syncthreads();                       // new h0 visible

    // ---- layer 1: init with bias, then Wih1 @ h0_new + Whh1 @ h1_old ----
#pragma unroll
    for (int g = 0; g < 4; ++g) {
        const int j = g * 128 + hh0;
        unsigned long long bv = pk2(sm->b1s[j], sm->b1s[j + 1]);
#pragma unroll
        for (int r = 0; r < 8; ++r) acc[g * 8 + r] = bv;
    }
    mv128(WTih1, sm->h0s, r0, hh0, acc);
    mv128(WThh1, sm->h1s, r0, hh0, acc);
    __syncthreads();                       // everyone done reading old h1
    gate_update(acc, sm->c1s, sm->h1s, r0, hh0);
    __syncthreads();                       // new h1 visible
}

__global__ void __launch_bounds__(NTH, 2)
lstm_kernel(const float* __restrict__ x,
            const float* __restrict__ eWih0, const float* __restrict__ eb0,
            const float* __restrict__ eb1,
            const float* __restrict__ dWih0, const float* __restrict__ db0,
            const float* __restrict__ db1,
            const float* __restrict__ fcW, const float* __restrict__ fcb,
            float* __restrict__ out, int B)
{
    extern __shared__ char smraw[];
    SM* sm = (SM*)smraw;

    const int tid = threadIdx.x;
    const int r0 = (tid >> 6) * 8;        // 4 row groups of 8 rows
    const int hh0 = (tid & 63) * 2;       // 64 hidden groups of 2
    const int bbase = blockIdx.x * BT;

    // Load this tile's input sequence (coalesced)
    for (int i = tid; i < BT * 90; i += NTH)
        sm->xs[i / 90][i % 90] = x[(size_t)(bbase + i / 90) * 90 + (i % 90)];
    for (int i = tid; i < 768; i += NTH) sm->fcWs[i] = fcW[i];
    if (tid < 6) sm->fcbs[tid] = fcb[tid];
    // encoder small weights
    for (int i = tid; i < 1536; i += NTH) sm->wih0s[i] = eWih0[i];
    for (int i = tid; i < 512; i += NTH) { sm->b0s[i] = eb0[i]; sm->b1s[i] = eb1[i]; }
    // zero states
#pragma unroll
    for (int r = 0; r < 8; ++r) {
        *(float2*)&sm->h0s[r0 + r][hh0] = make_float2(0.f, 0.f);
        *(float2*)&sm->h1s[r0 + r][hh0] = make_float2(0.f, 0.f);
        *(float2*)&sm->c0s[r0 + r][hh0] = make_float2(0.f, 0.f);
        *(float2*)&sm->c1s[r0 + r][hh0] = make_float2(0.f, 0.f);
    }
    __syncthreads();

    // ---------------- encoder ----------------
    for (int t = 0; t < 30; ++t) {
        float xr[8][3];
#pragma unroll
        for (int r = 0; r < 8; ++r) {
            xr[r][0] = sm->xs[r0 + r][3 * t + 0];
            xr[r][1] = sm->xs[r0 + r][3 * t + 1];
            xr[r][2] = sm->xs[r0 + r][3 * t + 2];
        }
        step(sm, xr, g_WT[0], g_WT[1], g_WT[2], r0, hh0);
    }

    // swap in decoder small weights; seed decoder input with x[:, -1, :]
    for (int i = tid; i < 1536; i += NTH) sm->wih0s[i] = dWih0[i];
    for (int i = tid; i < 512; i += NTH) { sm->b0s[i] = db0[i]; sm->b1s[i] = db1[i]; }
    if (tid < 96) sm->xcur[tid / 3][tid % 3] = sm->xs[tid / 3][87 + (tid % 3)];
    __syncthreads();

    // ---------------- decoder ----------------
    const size_t logvar_off = (size_t)B * 90;
    for (int t = 0; t < 30; ++t) {
        float xr[8][3];
#pragma unroll
        for (int r = 0; r < 8; ++r) {
            xr[r][0] = sm->xcur[r0 + r][0];
            xr[r][1] = sm->xcur[r0 + r][1];
            xr[r][2] = sm->xcur[r0 + r][2];
        }
        step(sm, xr, g_WT[3], g_WT[4], g_WT[5], r0, hh0);

        // fc: stats = h1 @ fc_W^T + fc_b  (6 outputs x 32 rows = 192 threads)
        if (tid < 192) {
            int row = tid & 31;
            int o = tid >> 5;     // 0..5
            const float* w = &sm->fcWs[o * 128];
            const float* hv = sm->h1s[row];
            float s0 = 0.f, s1 = 0.f, s2 = 0.f, s3 = 0.f;
#pragma unroll 8
            for (int k = 0; k < 128; k += 4) {
                s0 += w[k] * hv[k];
                s1 += w[k + 1] * hv[k + 1];
                s2 += w[k + 2] * hv[k + 2];
                s3 += w[k + 3] * hv[k + 3];
            }
            float s = sm->fcbs[o] + (s0 + s1) + (s2 + s3);
            size_t base = ((size_t)(bbase + row) * 30 + t) * 3;
            if (o < 3) {
                out[base + o] = s;
                sm->xcur[row][o] = s;      // feedback for next step
            } else {
                out[logvar_off + base + (o - 3)] = s;
            }
        }
        __syncthreads();   // xcur visible for next timestep
    }
}

extern "C" void kernel_launch(void* const* d_in, const int* in_sizes, int n_in,
                              void* d_out, int out_size)
{
    const float* x     = (const float*)d_in[0];
    const float* eWih0 = (const float*)d_in[1];
    const float* eWhh0 = (const float*)d_in[2];
    const float* eb0   = (const float*)d_in[3];
    const float* eWih1 = (const float*)d_in[4];
    const float* eWhh1 = (const float*)d_in[5];
    const float* eb1   = (const float*)d_in[6];
    const float* dWih0 = (const float*)d_in[7];
    const float* dWhh0 = (const float*)d_in[8];
    const float* db0   = (const float*)d_in[9];
    const float* dWih1 = (const float*)d_in[10];
    const float* dWhh1 = (const float*)d_in[11];
    const float* db1   = (const float*)d_in[12];
    const float* fcW   = (const float*)d_in[13];
    const float* fcb   = (const float*)d_in[14];
    float* out = (float*)d_out;

    int B = in_sizes[0] / 90;   // T_IN * IN_DIM = 90

    cudaFuncSetAttribute(lstm_kernel, cudaFuncAttributeMaxDynamicSharedMemorySize,
                         (int)sizeof(SM));

    // Pre-transpose the six 512x128 matrices to [k][j] layout.
    transpose_w<<<(6 * 65536) / 256, 256>>>(eWhh0, eWih1, eWhh1, dWhh0, dWih1, dWhh1);

    lstm_kernel<<<B / BT, NTH, sizeof(SM)>>>(x, eWih0, eb0, eb1, dWih0, db0, db1,
                                             fcW, fcb, out, B);
}